// round 12
// baseline (speedup 1.0000x reference)
#include <cuda_runtime.h>
#include <cuda_bf16.h>
#include <cstdint>

// Problem constants: B=64, T=12, P=128, F=128, H=12, MAXC=48
#define Bdim   64
#define Tdim   12
#define Pdim   128
#define Fdim   128
#define Hdim   12
#define MAXC   48
#define Ddim   (Tdim * Fdim)        // 1536 (K)
#define NCdim  (MAXC * Hdim)        // 576  (GEMM N)
#define NNODES 4356

#define TN 64                       // CTA c-tile (no overlap: 576 = 9*64)
#define TK 32                       // K chunk (2 k16 steps)
#define NKC (Ddim / TK)             // 48
#define NTHREADS 128                // 4 warps: 2(M) x 2(N), each 32m x 32n
#define ASTR 40                     // bf16 row stride As[m][k]  (32 + 8)
#define BSTR 72                     // bf16 row stride Bs[k][c]  (64 + 8)

__device__ __forceinline__ unsigned smem_u32(const void* p) {
    return (unsigned)__cvta_generic_to_shared(p);
}

// split two fp32 into packed bf16 hi / lo pairs
__device__ __forceinline__ void split2(float x, float y, unsigned& hi, unsigned& lo) {
    __nv_bfloat16 hx = __float2bfloat16_rn(x);
    __nv_bfloat16 hy = __float2bfloat16_rn(y);
    __nv_bfloat16 lx = __float2bfloat16_rn(x - __bfloat162float(hx));
    __nv_bfloat16 ly = __float2bfloat16_rn(y - __bfloat162float(hy));
    hi = (unsigned)__bfloat16_as_ushort(hx) | ((unsigned)__bfloat16_as_ushort(hy) << 16);
    lo = (unsigned)__bfloat16_as_ushort(lx) | ((unsigned)__bfloat16_as_ushort(ly) << 16);
}

__device__ __forceinline__ void ldmx4(unsigned* r, unsigned addr) {
    asm volatile("ldmatrix.sync.aligned.m8n8.x4.shared.b16 {%0,%1,%2,%3}, [%4];"
                 : "=r"(r[0]), "=r"(r[1]), "=r"(r[2]), "=r"(r[3]) : "r"(addr));
}
__device__ __forceinline__ void ldmx4t(unsigned* r, unsigned addr) {
    asm volatile("ldmatrix.sync.aligned.m8n8.x4.trans.shared.b16 {%0,%1,%2,%3}, [%4];"
                 : "=r"(r[0]), "=r"(r[1]), "=r"(r[2]), "=r"(r[3]) : "r"(addr));
}
__device__ __forceinline__ void mma_bf16(float* c, const unsigned* a, unsigned b0, unsigned b1) {
    asm volatile(
        "mma.sync.aligned.m16n8k16.row.col.f32.bf16.bf16.f32 "
        "{%0,%1,%2,%3}, {%4,%5,%6,%7}, {%8,%9}, {%0,%1,%2,%3};"
        : "+f"(c[0]), "+f"(c[1]), "+f"(c[2]), "+f"(c[3])
        : "r"(a[0]), "r"(a[1]), "r"(a[2]), "r"(a[3]), "r"(b0), "r"(b1));
}

// 5 CTAs/SM -> 102-reg cap (no-spill margin); 20+ warps/SM residency
__global__ __launch_bounds__(NTHREADS, 5)
void patch_readout_bf16x3_sq_kernel(
    const float* __restrict__ x,        // [B, T, P, F]
    const float* __restrict__ W,        // [P, D, 576]
    const float* __restrict__ bias,     // [P, 576]
    const int*   __restrict__ node_map, // [P, MAXC]
    float*       __restrict__ out)      // [NNODES * B, H]
{
    const int p    = blockIdx.y;
    const int C0   = blockIdx.x * TN;
    const int tid  = threadIdx.x;
    const int lane = tid & 31;
    const int warp = tid >> 5;
    const int g    = lane >> 2;
    const int t    = lane & 3;
    const int m_base = (warp >> 1) * 32;   // 2 M-groups of 32 batch rows
    const int n_base = (warp & 1) * 32;    // 2 N-groups of 32 cols

    // single-buffered smem (bulk-synchronous; cross-CTA interleave hides load phase)
    __shared__ __align__(16) __nv_bfloat16 AsHi[64][ASTR];
    __shared__ __align__(16) __nv_bfloat16 AsLo[64][ASTR];
    __shared__ __align__(16) __nv_bfloat16 BsHi[TK][BSTR];
    __shared__ __align__(16) __nv_bfloat16 BsLo[TK][BSTR];

    const unsigned aHiB = smem_u32(AsHi), aLoB = smem_u32(AsLo);
    const unsigned bHiB = smem_u32(BsHi), bLoB = smem_u32(BsLo);

    const float* xp = x + p * Fdim;
    const float* Wp = W + (long long)p * Ddim * NCdim;

    // ---- fill roles (128 threads) ----
    const int a_m  = tid >> 1;           // 0..63 batch row
    const int a_k0 = (tid & 1) * 16;     // 16 k-values per thread
    const int b_d  = tid >> 2;           // 0..31 W row within chunk
    const int b_c0 = (tid & 3) * 16;     // 16 c-values per thread
    const long long a_row_off = (long long)a_m * (Tdim * Pdim * Fdim);

    // ---- ldmatrix per-lane address terms (element offsets) ----
    const int q  = lane >> 3;
    const int j7 = lane & 7;
    // A tiles (m16k16, non-trans): q0=(m0-7,k0-7) q1=(m8-15,k0-7) q2=(m0-7,k8-15) q3=(m8-15,k8-15)
    int aTerm[2];
    {
        const int rq = (q & 1) * 8 + j7;
        const int cq = (q >> 1) * 8;
        aTerm[0] = (m_base +  0 + rq) * ASTR + cq;
        aTerm[1] = (m_base + 16 + rq) * ASTR + cq;
    }
    // B tiles (k16n16, trans): regs 0,1 -> first n8; 2,3 -> second n8
    int bTerm[2];
    {
        const int rk = (q & 1) * 8 + j7;
        bTerm[0] = rk * BSTR + n_base +  0 + (q >> 1) * 8;
        bTerm[1] = rk * BSTR + n_base + 16 + (q >> 1) * 8;
    }

    float acc[2][4][4];                  // [m16 tile][n8 tile][frag]
    #pragma unroll
    for (int mi = 0; mi < 2; mi++)
        #pragma unroll
        for (int nj = 0; nj < 4; nj++)
            #pragma unroll
            for (int e = 0; e < 4; e++) acc[mi][nj][e] = 0.0f;

    for (int kc = 0; kc < NKC; kc++) {
        const int K0 = kc * TK;

        // ---- load phase: LDG issues before the sync, overlapping prior compute ----
        const int tt = K0 >> 7;
        const int f0 = K0 & 127;
        const float* ar = xp + a_row_off + tt * (Pdim * Fdim) + f0 + a_k0;
        float4 av0 = *reinterpret_cast<const float4*>(ar);
        float4 av1 = *reinterpret_cast<const float4*>(ar + 4);
        float4 av2 = *reinterpret_cast<const float4*>(ar + 8);
        float4 av3 = *reinterpret_cast<const float4*>(ar + 12);
        const float* br = Wp + (long long)(K0 + b_d) * NCdim + C0 + b_c0;
        float4 bv0 = *reinterpret_cast<const float4*>(br);
        float4 bv1 = *reinterpret_cast<const float4*>(br + 4);
        float4 bv2 = *reinterpret_cast<const float4*>(br + 8);
        float4 bv3 = *reinterpret_cast<const float4*>(br + 12);

        __syncthreads();   // prior compute done -> safe to overwrite buffer

        // ---- split + store ----
        {
            unsigned h[8], l[8];
            split2(av0.x, av0.y, h[0], l[0]); split2(av0.z, av0.w, h[1], l[1]);
            split2(av1.x, av1.y, h[2], l[2]); split2(av1.z, av1.w, h[3], l[3]);
            split2(av2.x, av2.y, h[4], l[4]); split2(av2.z, av2.w, h[5], l[5]);
            split2(av3.x, av3.y, h[6], l[6]); split2(av3.z, av3.w, h[7], l[7]);
            *reinterpret_cast<uint4*>(&AsHi[a_m][a_k0])     = make_uint4(h[0], h[1], h[2], h[3]);
            *reinterpret_cast<uint4*>(&AsHi[a_m][a_k0 + 8]) = make_uint4(h[4], h[5], h[6], h[7]);
            *reinterpret_cast<uint4*>(&AsLo[a_m][a_k0])     = make_uint4(l[0], l[1], l[2], l[3]);
            *reinterpret_cast<uint4*>(&AsLo[a_m][a_k0 + 8]) = make_uint4(l[4], l[5], l[6], l[7]);
        }
        {
            unsigned h[8], l[8];
            split2(bv0.x, bv0.y, h[0], l[0]); split2(bv0.z, bv0.w, h[1], l[1]);
            split2(bv1.x, bv1.y, h[2], l[2]); split2(bv1.z, bv1.w, h[3], l[3]);
            split2(bv2.x, bv2.y, h[4], l[4]); split2(bv2.z, bv2.w, h[5], l[5]);
            split2(bv3.x, bv3.y, h[6], l[6]); split2(bv3.z, bv3.w, h[7], l[7]);
            *reinterpret_cast<uint4*>(&BsHi[b_d][b_c0])     = make_uint4(h[0], h[1], h[2], h[3]);
            *reinterpret_cast<uint4*>(&BsHi[b_d][b_c0 + 8]) = make_uint4(h[4], h[5], h[6], h[7]);
            *reinterpret_cast<uint4*>(&BsLo[b_d][b_c0])     = make_uint4(l[0], l[1], l[2], l[3]);
            *reinterpret_cast<uint4*>(&BsLo[b_d][b_c0 + 8]) = make_uint4(l[4], l[5], l[6], l[7]);
        }

        __syncthreads();   // buffer filled -> safe to ldmatrix

        // ---- compute: 2 k16 steps, 24 MMAs each ----
        #pragma unroll
        for (int s = 0; s < 2; s++) {
            const int k0 = s * 16;
            unsigned aH[2][4], aL[2][4], bH[2][4], bL[2][4];
            #pragma unroll
            for (int mi = 0; mi < 2; mi++) {
                const unsigned ao = (unsigned)(aTerm[mi] + k0) * 2u;
                ldmx4(aH[mi], aHiB + ao);
                ldmx4(aL[mi], aLoB + ao);
            }
            #pragma unroll
            for (int nj = 0; nj < 2; nj++) {
                const unsigned bo = (unsigned)(bTerm[nj] + k0 * BSTR) * 2u;
                ldmx4t(bH[nj], bHiB + bo);
                ldmx4t(bL[nj], bLoB + bo);
            }
            #pragma unroll
            for (int mi = 0; mi < 2; mi++)
                #pragma unroll
                for (int nj = 0; nj < 4; nj++) {
                    const unsigned* bh = &bH[nj >> 1][(nj & 1) * 2];
                    const unsigned* bl = &bL[nj >> 1][(nj & 1) * 2];
                    mma_bf16(acc[mi][nj], aH[mi], bh[0], bh[1]);
                    mma_bf16(acc[mi][nj], aH[mi], bl[0], bl[1]);
                    mma_bf16(acc[mi][nj], aL[mi], bh[0], bh[1]);
                }
        }
    }

    // ---- epilogue: bias + permutation scatter ----
    // C frag: c0=(g,2t) c1=(g,2t+1) c2=(g+8,2t) c3=(g+8,2t+1)
    const int*   nm = node_map + p * MAXC;
    const float* bp = bias + p * NCdim;

    #pragma unroll
    for (int nj = 0; nj < 4; nj++) {
        const int cbase = C0 + n_base + nj * 8 + 2 * t;
        #pragma unroll
        for (int e = 0; e < 2; e++) {
            const int c = cbase + e;
            const int n = c / Hdim;
            const int h = c - n * Hdim;
            const int node = nm[n];
            if (node < NNODES) {
                const float bb = bp[c];
                float* op = out + (long long)node * (Bdim * Hdim) + h;
                #pragma unroll
                for (int mi = 0; mi < 2; mi++) {
                    const int r0 = m_base + mi * 16 + g;
                    op[(r0    ) * Hdim] = acc[mi][nj][e]     + bb;
                    op[(r0 + 8) * Hdim] = acc[mi][nj][2 + e] + bb;
                }
            }
        }
    }
}

extern "C" void kernel_launch(void* const* d_in, const int* in_sizes, int n_in,
                              void* d_out, int out_size)
{
    const float* x        = (const float*)d_in[0];
    const float* W        = (const float*)d_in[1];
    const float* bias     = (const float*)d_in[2];
    const int*   node_map = (const int*)d_in[3];
    float*       out      = (float*)d_out;

    dim3 grid(NCdim / TN, Pdim);   // (9, 128)
    dim3 block(NTHREADS);
    patch_readout_bf16x3_sq_kernel<<<grid, block>>>(x, W, bias, node_map, out);
}

// round 13
// speedup vs baseline: 1.2627x; 1.2627x over previous
#include <cuda_runtime.h>
#include <cuda_bf16.h>
#include <cstdint>

// Problem constants: B=64, T=12, P=128, F=128, H=12, MAXC=48
#define Bdim   64
#define Tdim   12
#define Pdim   128
#define Fdim   128
#define Hdim   12
#define MAXC   48
#define Ddim   (Tdim * Fdim)        // 1536 (K)
#define NCdim  (MAXC * Hdim)        // 576  (GEMM N)
#define NNODES 4356

#define TN 96                       // CTA c-tile (576 = 6*96, exact)
#define TK 32                       // K chunk (2 k16 steps)
#define NKC (Ddim / TK)             // 48
#define NTHREADS 256                // 8 warps: 2(M) x 4(N), each 32m x 24n
#define ASTR 40                     // bf16 row stride As[m][k]  (32 + 8)
#define BSTR 104                    // bf16 row stride Bs[k][c]  (96 + 8) -> 208 B (16B-mult)

__device__ __forceinline__ unsigned smem_u32(const void* p) {
    return (unsigned)__cvta_generic_to_shared(p);
}

// split two fp32 into packed bf16 hi / lo pairs
__device__ __forceinline__ void split2(float x, float y, unsigned& hi, unsigned& lo) {
    __nv_bfloat16 hx = __float2bfloat16_rn(x);
    __nv_bfloat16 hy = __float2bfloat16_rn(y);
    __nv_bfloat16 lx = __float2bfloat16_rn(x - __bfloat162float(hx));
    __nv_bfloat16 ly = __float2bfloat16_rn(y - __bfloat162float(hy));
    hi = (unsigned)__bfloat16_as_ushort(hx) | ((unsigned)__bfloat16_as_ushort(hy) << 16);
    lo = (unsigned)__bfloat16_as_ushort(lx) | ((unsigned)__bfloat16_as_ushort(ly) << 16);
}

__device__ __forceinline__ void ldmx4(unsigned* r, unsigned addr) {
    asm volatile("ldmatrix.sync.aligned.m8n8.x4.shared.b16 {%0,%1,%2,%3}, [%4];"
                 : "=r"(r[0]), "=r"(r[1]), "=r"(r[2]), "=r"(r[3]) : "r"(addr));
}
__device__ __forceinline__ void ldmx4t(unsigned* r, unsigned addr) {
    asm volatile("ldmatrix.sync.aligned.m8n8.x4.trans.shared.b16 {%0,%1,%2,%3}, [%4];"
                 : "=r"(r[0]), "=r"(r[1]), "=r"(r[2]), "=r"(r[3]) : "r"(addr));
}
__device__ __forceinline__ void ldmx2t(unsigned* r, unsigned addr) {
    asm volatile("ldmatrix.sync.aligned.m8n8.x2.trans.shared.b16 {%0,%1}, [%2];"
                 : "=r"(r[0]), "=r"(r[1]) : "r"(addr));
}
__device__ __forceinline__ void mma_bf16(float* c, const unsigned* a, unsigned b0, unsigned b1) {
    asm volatile(
        "mma.sync.aligned.m16n8k16.row.col.f32.bf16.bf16.f32 "
        "{%0,%1,%2,%3}, {%4,%5,%6,%7}, {%8,%9}, {%0,%1,%2,%3};"
        : "+f"(c[0]), "+f"(c[1]), "+f"(c[2]), "+f"(c[3])
        : "r"(a[0]), "r"(a[1]), "r"(a[2]), "r"(a[3]), "r"(b0), "r"(b1));
}

// min 3 CTAs/SM -> 85-reg cap -> 24 warps/SM
__global__ __launch_bounds__(NTHREADS, 3)
void patch_readout_bf16x3_n24_kernel(
    const float* __restrict__ x,        // [B, T, P, F]
    const float* __restrict__ W,        // [P, D, 576]
    const float* __restrict__ bias,     // [P, 576]
    const int*   __restrict__ node_map, // [P, MAXC]
    float*       __restrict__ out)      // [NNODES * B, H]
{
    const int p    = blockIdx.y;
    const int C0   = blockIdx.x * TN;
    const int tid  = threadIdx.x;
    const int lane = tid & 31;
    const int warp = tid >> 5;
    const int g    = lane >> 2;
    const int t    = lane & 3;
    const int m_base = (warp >> 2) * 32;   // 2 M-groups of 32 rows
    const int n_base = (warp & 3) * 24;    // 4 N-groups of 24 cols

    __shared__ __align__(16) __nv_bfloat16 AsHi[2][64][ASTR];
    __shared__ __align__(16) __nv_bfloat16 AsLo[2][64][ASTR];
    __shared__ __align__(16) __nv_bfloat16 BsHi[2][TK][BSTR];
    __shared__ __align__(16) __nv_bfloat16 BsLo[2][TK][BSTR];

    const unsigned aHiB = smem_u32(AsHi), aLoB = smem_u32(AsLo);
    const unsigned bHiB = smem_u32(BsHi), bLoB = smem_u32(BsLo);
    const unsigned ABUF = 64 * ASTR * 2;
    const unsigned BBUF = TK * BSTR * 2;

    const float* xp = x + p * Fdim;
    const float* Wp = W + (long long)p * Ddim * NCdim;

    // ---- fill roles ----
    const int a_m  = tid >> 2;          // 0..63 batch row
    const int a_kq = (tid & 3) * 8;     // k octet
    const int b_d  = tid >> 3;          // 0..31 W row within chunk
    const int b_c  = (tid & 7) * 4;     // c quad base; +32*i strided (i=0..2)
    const long long a_row_off = (long long)a_m * (Tdim * Pdim * Fdim);

    // ---- ldmatrix per-lane address terms ----
    const int q  = lane >> 3;
    const int j7 = lane & 7;
    int rowTermA[2];
    {
        const int rq = (q & 1) * 8 + j7;
        const int cq = (q >> 1) * 8;
        rowTermA[0] = (m_base +  0 + rq) * ASTR + cq;
        rowTermA[1] = (m_base + 16 + rq) * ASTR + cq;
    }
    // x4t: covers n8 blocks 0,1 (regs 0,1 -> n8#0 ; regs 2,3 -> n8#1)
    const int rowTermB4 = ((q & 1) * 8 + j7) * BSTR + n_base + (q >> 1) * 8;
    // x2t: covers n8 block 2 (regs 0,1 = b0,b1); addr lanes 0..15
    const int rowTermB2 = (((lane >> 3) & 1) * 8 + j7) * BSTR + n_base + 16;

    float acc[2][3][4];                  // [m16 tile][n8 tile][frag]
    #pragma unroll
    for (int i = 0; i < 2; i++)
        #pragma unroll
        for (int jj = 0; jj < 3; jj++)
            #pragma unroll
            for (int r = 0; r < 4; r++) acc[i][jj][r] = 0.0f;

    float4 av0, av1, bq0, bq1, bq2;

    auto load_chunk = [&](int kc) {
        const int K0 = kc * TK;
        const int tt = K0 >> 7;
        const int f0 = K0 & 127;
        const float* ap = xp + a_row_off + tt * (Pdim * Fdim) + f0 + a_kq;
        av0 = *reinterpret_cast<const float4*>(ap);
        av1 = *reinterpret_cast<const float4*>(ap + 4);
        const float* bp = Wp + (long long)(K0 + b_d) * NCdim + C0 + b_c;
        bq0 = *reinterpret_cast<const float4*>(bp);
        bq1 = *reinterpret_cast<const float4*>(bp + 32);
        bq2 = *reinterpret_cast<const float4*>(bp + 64);
    };
    auto store_chunk = [&](int buf) {
        // A: natural rows
        {
            unsigned h0, l0, h1, l1, h2, l2, h3, l3;
            split2(av0.x, av0.y, h0, l0); split2(av0.z, av0.w, h1, l1);
            split2(av1.x, av1.y, h2, l2); split2(av1.z, av1.w, h3, l3);
            *reinterpret_cast<uint4*>(&AsHi[buf][a_m][a_kq]) = make_uint4(h0, h1, h2, h3);
            *reinterpret_cast<uint4*>(&AsLo[buf][a_m][a_kq]) = make_uint4(l0, l1, l2, l3);
        }
        // B: three strided c-quads per thread (c = b_c + 32*i)
        {
            unsigned h0, l0, h1, l1;
            split2(bq0.x, bq0.y, h0, l0); split2(bq0.z, bq0.w, h1, l1);
            *reinterpret_cast<uint2*>(&BsHi[buf][b_d][b_c])      = make_uint2(h0, h1);
            *reinterpret_cast<uint2*>(&BsLo[buf][b_d][b_c])      = make_uint2(l0, l1);
            split2(bq1.x, bq1.y, h0, l0); split2(bq1.z, bq1.w, h1, l1);
            *reinterpret_cast<uint2*>(&BsHi[buf][b_d][b_c + 32]) = make_uint2(h0, h1);
            *reinterpret_cast<uint2*>(&BsLo[buf][b_d][b_c + 32]) = make_uint2(l0, l1);
            split2(bq2.x, bq2.y, h0, l0); split2(bq2.z, bq2.w, h1, l1);
            *reinterpret_cast<uint2*>(&BsHi[buf][b_d][b_c + 64]) = make_uint2(h0, h1);
            *reinterpret_cast<uint2*>(&BsLo[buf][b_d][b_c + 64]) = make_uint2(l0, l1);
        }
    };

    load_chunk(0);
    store_chunk(0);
    __syncthreads();

    for (int kc = 0; kc < NKC; kc++) {
        const int buf = kc & 1;
        const bool more = (kc + 1 < NKC);
        if (more) load_chunk(kc + 1);

        #pragma unroll
        for (int s = 0; s < 2; s++) {
            const int k0 = s * 16;
            unsigned aH[2][4], aL[2][4], bH4[4], bL4[4], bH2[2], bL2[2];
            #pragma unroll
            for (int i = 0; i < 2; i++) {
                const unsigned ao = buf * ABUF + (unsigned)(rowTermA[i] + k0) * 2u;
                ldmx4(aH[i], aHiB + ao);
                ldmx4(aL[i], aLoB + ao);
            }
            {
                const unsigned bo4 = buf * BBUF + (unsigned)(rowTermB4 + k0 * BSTR) * 2u;
                ldmx4t(bH4, bHiB + bo4);
                ldmx4t(bL4, bLoB + bo4);
                const unsigned bo2 = buf * BBUF + (unsigned)(rowTermB2 + k0 * BSTR) * 2u;
                ldmx2t(bH2, bHiB + bo2);
                ldmx2t(bL2, bLoB + bo2);
            }
            #pragma unroll
            for (int i = 0; i < 2; i++) {
                #pragma unroll
                for (int jj = 0; jj < 2; jj++) {
                    mma_bf16(acc[i][jj], aH[i], bH4[2 * jj], bH4[2 * jj + 1]);
                    mma_bf16(acc[i][jj], aH[i], bL4[2 * jj], bL4[2 * jj + 1]);
                    mma_bf16(acc[i][jj], aL[i], bH4[2 * jj], bH4[2 * jj + 1]);
                }
                mma_bf16(acc[i][2], aH[i], bH2[0], bH2[1]);
                mma_bf16(acc[i][2], aH[i], bL2[0], bL2[1]);
                mma_bf16(acc[i][2], aL[i], bH2[0], bH2[1]);
            }
        }

        if (more) {
            store_chunk(buf ^ 1);
            __syncthreads();
        }
    }

    // ---- epilogue: bias + permutation scatter ----
    // C frag: c0=(g,2t) c1=(g,2t+1) c2=(g+8,2t) c3=(g+8,2t+1)
    const int*   nm = node_map + p * MAXC;
    const float* bp = bias + p * NCdim;

    #pragma unroll
    for (int jj = 0; jj < 3; jj++) {
        const int cbase = C0 + n_base + jj * 8 + 2 * t;
        #pragma unroll
        for (int e = 0; e < 2; e++) {
            const int c = cbase + e;
            const int n = c / Hdim;
            const int h = c - n * Hdim;
            const int node = nm[n];
            if (node < NNODES) {
                const float bb = bp[c];
                float* op = out + (long long)node * (Bdim * Hdim) + h;
                #pragma unroll
                for (int i = 0; i < 2; i++) {
                    const int r0 = m_base + i * 16 + g;
                    op[(r0    ) * Hdim] = acc[i][jj][e]     + bb;
                    op[(r0 + 8) * Hdim] = acc[i][jj][2 + e] + bb;
                }
            }
        }
    }
}

extern "C" void kernel_launch(void* const* d_in, const int* in_sizes, int n_in,
                              void* d_out, int out_size)
{
    const float* x        = (const float*)d_in[0];
    const float* W        = (const float*)d_in[1];
    const float* bias     = (const float*)d_in[2];
    const int*   node_map = (const int*)d_in[3];
    float*       out      = (float*)d_out;

    dim3 grid(NCdim / TN, Pdim);   // (6, 128)
    dim3 block(NTHREADS);
    patch_readout_bf16x3_n24_kernel<<<grid, block>>>(x, W, bias, node_map, out);
}

// round 14
// speedup vs baseline: 1.6311x; 1.2918x over previous
#include <cuda_runtime.h>
#include <cuda_fp16.h>
#include <cstdint>

// Problem constants: B=64, T=12, P=128, F=128, H=12, MAXC=48
#define Bdim   64
#define Tdim   12
#define Pdim   128
#define Fdim   128
#define Hdim   12
#define MAXC   48
#define Ddim   (Tdim * Fdim)        // 1536 (K)
#define NCdim  (MAXC * Hdim)        // 576  (GEMM N)
#define NNODES 4356

#define TN 96                       // CTA c-tile (576 = 6*96, exact)
#define TK 32                       // K chunk (2 k16 steps)
#define NKC (Ddim / TK)             // 48
#define NTHREADS 256                // 8 warps: 2(M) x 4(N), each 32m x 24n
#define ASTR 40                     // fp16 row stride As[m][k]  (32 + 8)
#define BSTR 104                    // fp16 row stride Bs[k][c]  (96 + 8) -> 208 B

__device__ __forceinline__ unsigned smem_u32(const void* p) {
    return (unsigned)__cvta_generic_to_shared(p);
}

// pack two fp32 -> fp16x2 (single rounding; used for x / A operand)
__device__ __forceinline__ unsigned pack2h(float x, float y) {
    __half2 h = __floats2half2_rn(x, y);
    return *reinterpret_cast<unsigned*>(&h);
}
// split two fp32 into fp16 hi/lo pairs (used for W / B operand)
__device__ __forceinline__ void splitW(float x, float y, unsigned& hi, unsigned& lo) {
    __half hx = __float2half_rn(x);
    __half hy = __float2half_rn(y);
    __half lx = __float2half_rn(x - __half2float(hx));
    __half ly = __float2half_rn(y - __half2float(hy));
    hi = (unsigned)__half_as_ushort(hx) | ((unsigned)__half_as_ushort(hy) << 16);
    lo = (unsigned)__half_as_ushort(lx) | ((unsigned)__half_as_ushort(ly) << 16);
}

__device__ __forceinline__ void ldmx4(unsigned* r, unsigned addr) {
    asm volatile("ldmatrix.sync.aligned.m8n8.x4.shared.b16 {%0,%1,%2,%3}, [%4];"
                 : "=r"(r[0]), "=r"(r[1]), "=r"(r[2]), "=r"(r[3]) : "r"(addr));
}
__device__ __forceinline__ void ldmx4t(unsigned* r, unsigned addr) {
    asm volatile("ldmatrix.sync.aligned.m8n8.x4.trans.shared.b16 {%0,%1,%2,%3}, [%4];"
                 : "=r"(r[0]), "=r"(r[1]), "=r"(r[2]), "=r"(r[3]) : "r"(addr));
}
__device__ __forceinline__ void ldmx2t(unsigned* r, unsigned addr) {
    asm volatile("ldmatrix.sync.aligned.m8n8.x2.trans.shared.b16 {%0,%1}, [%2];"
                 : "=r"(r[0]), "=r"(r[1]) : "r"(addr));
}
__device__ __forceinline__ void mma_f16(float* c, const unsigned* a, unsigned b0, unsigned b1) {
    asm volatile(
        "mma.sync.aligned.m16n8k16.row.col.f32.f16.f16.f32 "
        "{%0,%1,%2,%3}, {%4,%5,%6,%7}, {%8,%9}, {%0,%1,%2,%3};"
        : "+f"(c[0]), "+f"(c[1]), "+f"(c[2]), "+f"(c[3])
        : "r"(a[0]), "r"(a[1]), "r"(a[2]), "r"(a[3]), "r"(b0), "r"(b1));
}

// min 3 CTAs/SM -> 85-reg cap -> 24 warps/SM
__global__ __launch_bounds__(NTHREADS, 3)
void patch_readout_f16w2_kernel(
    const float* __restrict__ x,        // [B, T, P, F]
    const float* __restrict__ W,        // [P, D, 576]
    const float* __restrict__ bias,     // [P, 576]
    const int*   __restrict__ node_map, // [P, MAXC]
    float*       __restrict__ out)      // [NNODES * B, H]
{
    const int p    = blockIdx.y;
    const int C0   = blockIdx.x * TN;
    const int tid  = threadIdx.x;
    const int lane = tid & 31;
    const int warp = tid >> 5;
    const int g    = lane >> 2;
    const int t    = lane & 3;
    const int m_base = (warp >> 2) * 32;   // 2 M-groups of 32 rows
    const int n_base = (warp & 3) * 24;    // 4 N-groups of 24 cols

    __shared__ __align__(16) __half AsH [2][64][ASTR];   // x (single fp16)
    __shared__ __align__(16) __half BsHi[2][TK][BSTR];   // W hi
    __shared__ __align__(16) __half BsLo[2][TK][BSTR];   // W lo

    const unsigned aHB  = smem_u32(AsH);
    const unsigned bHiB = smem_u32(BsHi), bLoB = smem_u32(BsLo);
    const unsigned ABUF = 64 * ASTR * 2;
    const unsigned BBUF = TK * BSTR * 2;

    const float* xp = x + p * Fdim;
    const float* Wp = W + (long long)p * Ddim * NCdim;

    // ---- fill roles ----
    const int a_m  = tid >> 2;          // 0..63 batch row
    const int a_kq = (tid & 3) * 8;     // k octet
    const int b_d  = tid >> 3;          // 0..31 W row within chunk
    const int b_c  = (tid & 7) * 4;     // c quad base; +32*i strided (i=0..2)
    const long long a_row_off = (long long)a_m * (Tdim * Pdim * Fdim);

    // ---- ldmatrix per-lane address terms ----
    const int q  = lane >> 3;
    const int j7 = lane & 7;
    int rowTermA[2];
    {
        const int rq = (q & 1) * 8 + j7;
        const int cq = (q >> 1) * 8;
        rowTermA[0] = (m_base +  0 + rq) * ASTR + cq;
        rowTermA[1] = (m_base + 16 + rq) * ASTR + cq;
    }
    // x4t: n8 blocks 0,1 ; x2t: n8 block 2
    const int rowTermB4 = ((q & 1) * 8 + j7) * BSTR + n_base + (q >> 1) * 8;
    const int rowTermB2 = (((lane >> 3) & 1) * 8 + j7) * BSTR + n_base + 16;

    float acc[2][3][4];                  // [m16 tile][n8 tile][frag]
    #pragma unroll
    for (int i = 0; i < 2; i++)
        #pragma unroll
        for (int jj = 0; jj < 3; jj++)
            #pragma unroll
            for (int r = 0; r < 4; r++) acc[i][jj][r] = 0.0f;

    float4 av0, av1, bq0, bq1, bq2;

    auto load_chunk = [&](int kc) {
        const int K0 = kc * TK;
        const int tt = K0 >> 7;
        const int f0 = K0 & 127;
        const float* ap = xp + a_row_off + tt * (Pdim * Fdim) + f0 + a_kq;
        av0 = *reinterpret_cast<const float4*>(ap);
        av1 = *reinterpret_cast<const float4*>(ap + 4);
        const float* bp = Wp + (long long)(K0 + b_d) * NCdim + C0 + b_c;
        bq0 = *reinterpret_cast<const float4*>(bp);
        bq1 = *reinterpret_cast<const float4*>(bp + 32);
        bq2 = *reinterpret_cast<const float4*>(bp + 64);
    };
    auto store_chunk = [&](int buf) {
        // A: x -> fp16, natural rows
        *reinterpret_cast<uint4*>(&AsH[buf][a_m][a_kq]) =
            make_uint4(pack2h(av0.x, av0.y), pack2h(av0.z, av0.w),
                       pack2h(av1.x, av1.y), pack2h(av1.z, av1.w));
        // B: W -> fp16 hi/lo, three strided c-quads per thread
        {
            unsigned h0, l0, h1, l1;
            splitW(bq0.x, bq0.y, h0, l0); splitW(bq0.z, bq0.w, h1, l1);
            *reinterpret_cast<uint2*>(&BsHi[buf][b_d][b_c])      = make_uint2(h0, h1);
            *reinterpret_cast<uint2*>(&BsLo[buf][b_d][b_c])      = make_uint2(l0, l1);
            splitW(bq1.x, bq1.y, h0, l0); splitW(bq1.z, bq1.w, h1, l1);
            *reinterpret_cast<uint2*>(&BsHi[buf][b_d][b_c + 32]) = make_uint2(h0, h1);
            *reinterpret_cast<uint2*>(&BsLo[buf][b_d][b_c + 32]) = make_uint2(l0, l1);
            splitW(bq2.x, bq2.y, h0, l0); splitW(bq2.z, bq2.w, h1, l1);
            *reinterpret_cast<uint2*>(&BsHi[buf][b_d][b_c + 64]) = make_uint2(h0, h1);
            *reinterpret_cast<uint2*>(&BsLo[buf][b_d][b_c + 64]) = make_uint2(l0, l1);
        }
    };

    load_chunk(0);
    store_chunk(0);
    __syncthreads();

    for (int kc = 0; kc < NKC; kc++) {
        const int buf = kc & 1;
        const bool more = (kc + 1 < NKC);
        if (more) load_chunk(kc + 1);

        #pragma unroll
        for (int s = 0; s < 2; s++) {
            const int k0 = s * 16;
            unsigned aH[2][4], bH4[4], bL4[4], bH2[2], bL2[2];
            #pragma unroll
            for (int i = 0; i < 2; i++) {
                const unsigned ao = buf * ABUF + (unsigned)(rowTermA[i] + k0) * 2u;
                ldmx4(aH[i], aHB + ao);
            }
            {
                const unsigned bo4 = buf * BBUF + (unsigned)(rowTermB4 + k0 * BSTR) * 2u;
                ldmx4t(bH4, bHiB + bo4);
                ldmx4t(bL4, bLoB + bo4);
                const unsigned bo2 = buf * BBUF + (unsigned)(rowTermB2 + k0 * BSTR) * 2u;
                ldmx2t(bH2, bHiB + bo2);
                ldmx2t(bL2, bLoB + bo2);
            }
            #pragma unroll
            for (int i = 0; i < 2; i++) {
                #pragma unroll
                for (int jj = 0; jj < 2; jj++) {
                    mma_f16(acc[i][jj], aH[i], bH4[2 * jj], bH4[2 * jj + 1]);
                    mma_f16(acc[i][jj], aH[i], bL4[2 * jj], bL4[2 * jj + 1]);
                }
                mma_f16(acc[i][2], aH[i], bH2[0], bH2[1]);
                mma_f16(acc[i][2], aH[i], bL2[0], bL2[1]);
            }
        }

        if (more) {
            store_chunk(buf ^ 1);
            __syncthreads();
        }
    }

    // ---- epilogue: bias + permutation scatter ----
    // C frag: c0=(g,2t) c1=(g,2t+1) c2=(g+8,2t) c3=(g+8,2t+1)
    const int*   nm = node_map + p * MAXC;
    const float* bp = bias + p * NCdim;

    #pragma unroll
    for (int jj = 0; jj < 3; jj++) {
        const int cbase = C0 + n_base + jj * 8 + 2 * t;
        #pragma unroll
        for (int e = 0; e < 2; e++) {
            const int c = cbase + e;
            const int n = c / Hdim;
            const int h = c - n * Hdim;
            const int node = nm[n];
            if (node < NNODES) {
                const float bb = bp[c];
                float* op = out + (long long)node * (Bdim * Hdim) + h;
                #pragma unroll
                for (int i = 0; i < 2; i++) {
                    const int r0 = m_base + i * 16 + g;
                    op[(r0    ) * Hdim] = acc[i][jj][e]     + bb;
                    op[(r0 + 8) * Hdim] = acc[i][jj][2 + e] + bb;
                }
            }
        }
    }
}

extern "C" void kernel_launch(void* const* d_in, const int* in_sizes, int n_in,
                              void* d_out, int out_size)
{
    const float* x        = (const float*)d_in[0];
    const float* W        = (const float*)d_in[1];
    const float* bias     = (const float*)d_in[2];
    const int*   node_map = (const int*)d_in[3];
    float*       out      = (float*)d_out;

    dim3 grid(NCdim / TN, Pdim);   // (6, 128)
    dim3 block(NTHREADS);
    patch_readout_f16w2_kernel<<<grid, block>>>(x, W, bias, node_map, out);
}

// round 15
// speedup vs baseline: 2.0019x; 1.2273x over previous
#include <cuda_runtime.h>
#include <cuda_fp16.h>
#include <cstdint>

// Problem constants: B=64, T=12, P=128, F=128, H=12, MAXC=48
#define Bdim   64
#define Tdim   12
#define Pdim   128
#define Fdim   128
#define Hdim   12
#define MAXC   48
#define Ddim   (Tdim * Fdim)        // 1536 (K)
#define NCdim  (MAXC * Hdim)        // 576  (GEMM N)
#define NNODES 4356

#define TN 96                       // CTA c-tile (576 = 6*96, exact)
#define TK 32                       // K chunk (2 k16 steps)
#define NKC (Ddim / TK)             // 48
#define NTHREADS 256                // 8 warps: 2(M) x 4(N), each 32m x 24n
#define ASTR 40                     // fp16 row stride As[m][k]  (32 + 8)
#define BSTR 104                    // fp16 row stride Bs[k][c]  (96 + 8) -> 208 B

__device__ __forceinline__ unsigned smem_u32(const void* p) {
    return (unsigned)__cvta_generic_to_shared(p);
}

// pack two fp32 -> fp16x2 (single rounding)
__device__ __forceinline__ unsigned pack2h(float x, float y) {
    __half2 h = __floats2half2_rn(x, y);
    return *reinterpret_cast<unsigned*>(&h);
}

__device__ __forceinline__ void ldmx4(unsigned* r, unsigned addr) {
    asm volatile("ldmatrix.sync.aligned.m8n8.x4.shared.b16 {%0,%1,%2,%3}, [%4];"
                 : "=r"(r[0]), "=r"(r[1]), "=r"(r[2]), "=r"(r[3]) : "r"(addr));
}
__device__ __forceinline__ void ldmx4t(unsigned* r, unsigned addr) {
    asm volatile("ldmatrix.sync.aligned.m8n8.x4.trans.shared.b16 {%0,%1,%2,%3}, [%4];"
                 : "=r"(r[0]), "=r"(r[1]), "=r"(r[2]), "=r"(r[3]) : "r"(addr));
}
__device__ __forceinline__ void ldmx2t(unsigned* r, unsigned addr) {
    asm volatile("ldmatrix.sync.aligned.m8n8.x2.trans.shared.b16 {%0,%1}, [%2];"
                 : "=r"(r[0]), "=r"(r[1]) : "r"(addr));
}
__device__ __forceinline__ void mma_f16(float* c, const unsigned* a, unsigned b0, unsigned b1) {
    asm volatile(
        "mma.sync.aligned.m16n8k16.row.col.f32.f16.f16.f32 "
        "{%0,%1,%2,%3}, {%4,%5,%6,%7}, {%8,%9}, {%0,%1,%2,%3};"
        : "+f"(c[0]), "+f"(c[1]), "+f"(c[2]), "+f"(c[3])
        : "r"(a[0]), "r"(a[1]), "r"(a[2]), "r"(a[3]), "r"(b0), "r"(b1));
}

// min 3 CTAs/SM -> 85-reg cap -> 24 warps/SM
__global__ __launch_bounds__(NTHREADS, 3)
void patch_readout_f16_kernel(
    const float* __restrict__ x,        // [B, T, P, F]
    const float* __restrict__ W,        // [P, D, 576]
    const float* __restrict__ bias,     // [P, 576]
    const int*   __restrict__ node_map, // [P, MAXC]
    float*       __restrict__ out)      // [NNODES * B, H]
{
    const int p    = blockIdx.y;
    const int C0   = blockIdx.x * TN;
    const int tid  = threadIdx.x;
    const int lane = tid & 31;
    const int warp = tid >> 5;
    const int g    = lane >> 2;
    const int t    = lane & 3;
    const int m_base = (warp >> 2) * 32;   // 2 M-groups of 32 rows
    const int n_base = (warp & 3) * 24;    // 4 N-groups of 24 cols

    __shared__ __align__(16) __half AsH[2][64][ASTR];   // x fp16
    __shared__ __align__(16) __half BsH[2][TK][BSTR];   // W fp16

    const unsigned aHB = smem_u32(AsH);
    const unsigned bHB = smem_u32(BsH);
    const unsigned ABUF = 64 * ASTR * 2;
    const unsigned BBUF = TK * BSTR * 2;

    const float* xp = x + p * Fdim;
    const float* Wp = W + (long long)p * Ddim * NCdim;

    // ---- fill roles ----
    const int a_m  = tid >> 2;          // 0..63 batch row
    const int a_kq = (tid & 3) * 8;     // k octet
    const int b_d  = tid >> 3;          // 0..31 W row within chunk
    const int b_c  = (tid & 7) * 4;     // c quad base; +32*i strided (i=0..2)
    const long long a_row_off = (long long)a_m * (Tdim * Pdim * Fdim);

    // ---- ldmatrix per-lane address terms ----
    const int q  = lane >> 3;
    const int j7 = lane & 7;
    int rowTermA[2];
    {
        const int rq = (q & 1) * 8 + j7;
        const int cq = (q >> 1) * 8;
        rowTermA[0] = (m_base +  0 + rq) * ASTR + cq;
        rowTermA[1] = (m_base + 16 + rq) * ASTR + cq;
    }
    // x4t: n8 blocks 0,1 ; x2t: n8 block 2
    const int rowTermB4 = ((q & 1) * 8 + j7) * BSTR + n_base + (q >> 1) * 8;
    const int rowTermB2 = (((lane >> 3) & 1) * 8 + j7) * BSTR + n_base + 16;

    float acc[2][3][4];                  // [m16 tile][n8 tile][frag]
    #pragma unroll
    for (int i = 0; i < 2; i++)
        #pragma unroll
        for (int jj = 0; jj < 3; jj++)
            #pragma unroll
            for (int r = 0; r < 4; r++) acc[i][jj][r] = 0.0f;

    float4 av0, av1, bq0, bq1, bq2;

    auto load_chunk = [&](int kc) {
        const int K0 = kc * TK;
        const int tt = K0 >> 7;
        const int f0 = K0 & 127;
        const float* ap = xp + a_row_off + tt * (Pdim * Fdim) + f0 + a_kq;
        av0 = *reinterpret_cast<const float4*>(ap);
        av1 = *reinterpret_cast<const float4*>(ap + 4);
        const float* bp = Wp + (long long)(K0 + b_d) * NCdim + C0 + b_c;
        bq0 = *reinterpret_cast<const float4*>(bp);
        bq1 = *reinterpret_cast<const float4*>(bp + 32);
        bq2 = *reinterpret_cast<const float4*>(bp + 64);
    };
    auto store_chunk = [&](int buf) {
        // A: x -> fp16, natural rows
        *reinterpret_cast<uint4*>(&AsH[buf][a_m][a_kq]) =
            make_uint4(pack2h(av0.x, av0.y), pack2h(av0.z, av0.w),
                       pack2h(av1.x, av1.y), pack2h(av1.z, av1.w));
        // B: W -> fp16, three strided c-quads per thread
        *reinterpret_cast<uint2*>(&BsH[buf][b_d][b_c]) =
            make_uint2(pack2h(bq0.x, bq0.y), pack2h(bq0.z, bq0.w));
        *reinterpret_cast<uint2*>(&BsH[buf][b_d][b_c + 32]) =
            make_uint2(pack2h(bq1.x, bq1.y), pack2h(bq1.z, bq1.w));
        *reinterpret_cast<uint2*>(&BsH[buf][b_d][b_c + 64]) =
            make_uint2(pack2h(bq2.x, bq2.y), pack2h(bq2.z, bq2.w));
    };

    load_chunk(0);
    store_chunk(0);
    __syncthreads();

    for (int kc = 0; kc < NKC; kc++) {
        const int buf = kc & 1;
        const bool more = (kc + 1 < NKC);
        if (more) load_chunk(kc + 1);

        #pragma unroll
        for (int s = 0; s < 2; s++) {
            const int k0 = s * 16;
            unsigned aH[2][4], bH4[4], bH2[2];
            #pragma unroll
            for (int i = 0; i < 2; i++) {
                const unsigned ao = buf * ABUF + (unsigned)(rowTermA[i] + k0) * 2u;
                ldmx4(aH[i], aHB + ao);
            }
            {
                const unsigned bo4 = buf * BBUF + (unsigned)(rowTermB4 + k0 * BSTR) * 2u;
                ldmx4t(bH4, bHB + bo4);
                const unsigned bo2 = buf * BBUF + (unsigned)(rowTermB2 + k0 * BSTR) * 2u;
                ldmx2t(bH2, bHB + bo2);
            }
            #pragma unroll
            for (int i = 0; i < 2; i++) {
                mma_f16(acc[i][0], aH[i], bH4[0], bH4[1]);
                mma_f16(acc[i][1], aH[i], bH4[2], bH4[3]);
                mma_f16(acc[i][2], aH[i], bH2[0], bH2[1]);
            }
        }

        if (more) {
            store_chunk(buf ^ 1);
            __syncthreads();
        }
    }

    // ---- epilogue: bias + permutation scatter ----
    // C frag: c0=(g,2t) c1=(g,2t+1) c2=(g+8,2t) c3=(g+8,2t+1)
    const int*   nm = node_map + p * MAXC;
    const float* bp = bias + p * NCdim;

    #pragma unroll
    for (int jj = 0; jj < 3; jj++) {
        const int cbase = C0 + n_base + jj * 8 + 2 * t;
        #pragma unroll
        for (int e = 0; e < 2; e++) {
            const int c = cbase + e;
            const int n = c / Hdim;
            const int h = c - n * Hdim;
            const int node = nm[n];
            if (node < NNODES) {
                const float bb = bp[c];
                float* op = out + (long long)node * (Bdim * Hdim) + h;
                #pragma unroll
                for (int i = 0; i < 2; i++) {
                    const int r0 = m_base + i * 16 + g;
                    op[(r0    ) * Hdim] = acc[i][jj][e]     + bb;
                    op[(r0 + 8) * Hdim] = acc[i][jj][2 + e] + bb;
                }
            }
        }
    }
}

extern "C" void kernel_launch(void* const* d_in, const int* in_sizes, int n_in,
                              void* d_out, int out_size)
{
    const float* x        = (const float*)d_in[0];
    const float* W        = (const float*)d_in[1];
    const float* bias     = (const float*)d_in[2];
    const int*   node_map = (const int*)d_in[3];
    float*       out      = (float*)d_out;

    dim3 grid(NCdim / TN, Pdim);   // (6, 128)
    dim3 block(NTHREADS);
    patch_readout_f16_kernel<<<grid, block>>>(x, W, bias, node_map, out);
}